// round 6
// baseline (speedup 1.0000x reference)
#include <cuda_runtime.h>

#define SS    21     // search size
#define PAD   10
#define BS    4      // block size
#define NB    2      // blocks per CTA (horizontal)
#define TILE  24     // rows: BS + SS - 1
#define TC    28     // tile cols: NB*BS + SS - 1
#define NT    192    // threads: NB * 96
#define H     256
#define W     256

__global__ __launch_bounds__(NT)
void pred_kernel(const float* __restrict__ im1,
                 const float* __restrict__ im2,
                 float* __restrict__ out)
{
    __shared__ __align__(16) float im2t[TILE * TC];   // 672 floats, pitch == 28
    __shared__ float im1t[NB * 16];
    __shared__ float red[NB][16][21];  // per-pixel partial weighted sums over i
    __shared__ float sg[NB][21];       // per-i group min, then per-i weight-sum
    __shared__ float s_min[NB];

    const int t  = threadIdx.x;
    const int bx = blockIdx.x, by = blockIdx.y, b = blockIdx.z;
    const float* i1 = im1 + b * H * W;
    const float* i2 = im2 + b * H * W;

    const int x0 = bx * (NB * BS) - PAD;   // even
    const int y0 = by * BS - PAD;

    // ---- Phase 0: load 24x28 im2 halo tile (shared by both sub-blocks) ----
    if (bx >= 2 && bx <= 29 && by >= 3 && by <= 60) {
        // interior: coalesced float2 (x0 even). 336 float2 over 192 threads.
        #pragma unroll
        for (int p = 0; p < 2; p++) {
            int idx = t + p * NT;
            if (idx < TILE * (TC / 2)) {
                int r  = idx / (TC / 2);
                int c2 = idx - r * (TC / 2);
                float2 v = *(const float2*)(i2 + (y0 + r) * W + x0 + c2 * 2);
                *(float2*)&im2t[r * TC + c2 * 2] = v;
            }
        }
    } else {
        // border: predicated zero-pad
        #pragma unroll
        for (int q = 0; q < 4; q++) {
            int idx = t + q * NT;
            if (idx < TILE * TC) {
                int r = idx / TC, c = idx - r * TC;
                int y = y0 + r, x = x0 + c;
                float v = 0.0f;
                if ((unsigned)y < (unsigned)H && (unsigned)x < (unsigned)W)
                    v = i2[y * W + x];
                im2t[r * TC + c] = v;
            }
        }
    }
    if (t < NB * 16) {
        int s = t >> 4, w16 = t & 15;
        int py = w16 >> 2, px = w16 & 3;
        im1t[t] = i1[(by * BS + py) * W + bx * (NB * BS) + s * BS + px];
    }
    __syncthreads();

    // ---- mapping: s = sub-block, u = thread within sub-block, u = 4*i + py ----
    const int s  = t / 96;
    const int u  = t - s * 96;
    const int i  = u >> 2;          // shift row 0..20
    const int py = u & 3;           // pixel row 0..3
    const bool act = (u < 84);
    const unsigned gmask = (u >= 64) ? 0x000FFFFFu : 0xFFFFFFFFu;

    float r[TILE];                  // register-resident im2 row (py+i), cols s*4..s*4+23
    float vol[SS];

    if (act) {
        const float4* rp = (const float4*)&im2t[(py + i) * TC + s * BS]; // 16B aligned
        #pragma unroll
        for (int q = 0; q < 6; q++) {
            float4 v = rp[q];
            r[q * 4 + 0] = v.x; r[q * 4 + 1] = v.y;
            r[q * 4 + 2] = v.z; r[q * 4 + 3] = v.w;
        }
        const float a0 = im1t[s * 16 + py * 4 + 0], a1 = im1t[s * 16 + py * 4 + 1];
        const float a2 = im1t[s * 16 + py * 4 + 2], a3 = im1t[s * 16 + py * 4 + 3];

        #pragma unroll
        for (int j = 0; j < SS; j++) {
            vol[j] = fabsf(a0 - r[j])     + fabsf(a1 - r[j + 1])
                   + fabsf(a2 - r[j + 2]) + fabsf(a3 - r[j + 3]);
        }
        // allreduce over py within 4-lane group
        #pragma unroll
        for (int j = 0; j < SS; j++) {
            vol[j] += __shfl_xor_sync(gmask, vol[j], 1);
            vol[j] += __shfl_xor_sync(gmask, vol[j], 2);
        }
        float lmin = vol[0];
        #pragma unroll
        for (int j = 1; j < SS; j++) lmin = fminf(lmin, vol[j]);
        if (py == 0) sg[s][i] = lmin;
    }
    __syncthreads();

    // ---- second-level min over 21 rows: warp w handles sub-block w ----
    if (t < NB * 32) {
        int ws = t >> 5, lane = t & 31;
        float v = (lane < SS) ? sg[ws][lane] : 1e30f;
        #pragma unroll
        for (int o = 16; o; o >>= 1)
            v = fminf(v, __shfl_xor_sync(0xffffffffu, v, o));
        if (lane == 0) s_min[ws] = v;
    }
    __syncthreads();

    // ---- Phase 3: fused weights + weighted accumulation ----
    if (act) {
        // w = exp(-6.25*(vol - vmin)) = 2^(K*vol + M), K = -6.25*log2(e)
        const float K = -9.016844005555897f;
        const float M = -K * s_min[s];
        float lsum = 0.0f;
        float acc0 = 0.f, acc1 = 0.f, acc2 = 0.f, acc3 = 0.f;
        #pragma unroll
        for (int j = 0; j < SS; j++) {
            float e = fmaf(vol[j], K, M);
            float wv;
            asm("ex2.approx.ftz.f32 %0, %1;" : "=f"(wv) : "f"(e));
            lsum += wv;
            acc0 = fmaf(wv, r[j],     acc0);
            acc1 = fmaf(wv, r[j + 1], acc1);
            acc2 = fmaf(wv, r[j + 2], acc2);
            acc3 = fmaf(wv, r[j + 3], acc3);
        }
        if (py == 0) sg[s][i] = lsum;
        red[s][py * 4 + 0][i] = acc0;
        red[s][py * 4 + 1][i] = acc1;
        red[s][py * 4 + 2][i] = acc2;
        red[s][py * 4 + 3][i] = acc3;
    }
    __syncthreads();

    // ---- Phase 4: reduce over 21 shift-rows, normalize, store ----
    if (t < NB * 16) {
        int so = t >> 4, tt = t & 15;
        float sum = 0.0f;
        #pragma unroll
        for (int q = 0; q < SS; q++) sum += red[so][tt][q];
        float wsum = 0.0f;
        #pragma unroll
        for (int q = 0; q < SS; q++) wsum += sg[so][q];
        int py2 = tt >> 2, px2 = tt & 3;
        out[b * H * W + (by * BS + py2) * W + bx * (NB * BS) + so * BS + px2]
            = sum / wsum;
    }
}

extern "C" void kernel_launch(void* const* d_in, const int* in_sizes, int n_in,
                              void* d_out, int out_size) {
    const float* im1 = (const float*)d_in[0];
    const float* im2 = (const float*)d_in[1];
    float* out = (float*)d_out;
    dim3 grid(W / (NB * BS), H / BS, 2);   // (32, 64, 2)
    pred_kernel<<<grid, NT>>>(im1, im2, out);
}